// round 3
// baseline (speedup 1.0000x reference)
#include <cuda_runtime.h>
#include <cuda_bf16.h>

// ---------------------------------------------------------------------------
// Model_70222715289880: bilinear score -> top-k(10/64) -> gather of 10 tensors
// B=8, K=64, TOPK=10, N_R=4, L_R=128, H=512, D=128, D2=640.
//
// R3: parallelized score path. FP summation order of the bilinear dot is kept
// BIT-IDENTICAL to the R2 passing kernel (serial d-chain for q, 4-lane
// stride-4 chain + shfl pairs for the k-dot) — reordering risks flipping
// exact ties at the tanh saturation plateaus, which decide top-k membership.
// ---------------------------------------------------------------------------

#define Bq   8
#define Kk   64
#define TOPK 10
#define D2   640

#define OFF_SCORES   0
#define OFF_RATINGS  21238160
#define OFF_IDX      21248480

// vec4 (float4) offsets of gathered segments in dst
#define V4_SR    20u
#define V4_HR    40980u
#define V4_RA    5283860u
#define V4_RO    5294100u
#define V4_MASK  5304340u
#define V4_RB    5304420u
#define V4_RM    5306980u
#define V4_RE    5309560u

// gather-index range boundaries, in vec4 units
#define G_SR_END   40960u
#define G_HR_END   5283840u
#define G_RA_END   5294080u
#define G_RO_END   5304320u
#define G_MK_END   5304400u
#define G_RB_END   5306960u
#define G_RM_END   5309520u
#define G_RE_END   5312080u
#define G_TOTAL    5312080u

__device__ int   g_topk_idx[Bq * TOPK];
__device__ float g_q[Bq * D2];

// ---------------------------------------------------------------------------
// XLA's tanh (Eigen generic_fast_tanh_float as emitted by elemental_ir_emitter)
// ---------------------------------------------------------------------------
__device__ __forceinline__ float xla_tanhf(float x)
{
    const float kClamp = 7.90531110763549805f;
    float xc = fmaxf(-kClamp, fminf(x, kClamp));
    float x2 = xc * xc;

    float p = fmaf(x2, -2.76076847742355e-16f, 2.00018790482477e-13f);
    p = fmaf(x2, p, -8.60467152213735e-11f);
    p = fmaf(x2, p,  5.12229709037114e-08f);
    p = fmaf(x2, p,  1.48572235717979e-05f);
    p = fmaf(x2, p,  6.37261928875436e-04f);
    p = fmaf(x2, p,  4.89352455891786e-03f);
    p = xc * p;

    float q = fmaf(x2, 1.19825839466702e-06f, 1.18534705686654e-04f);
    q = fmaf(x2, q, 2.26843463243900e-03f);
    q = fmaf(x2, q, 4.89352518554385e-03f);

    float r = p / q;
    return (fabsf(x) < 0.0004f) ? x : r;
}

// total-order key on float (ascending), for tie-break-exact warp selection
__device__ __forceinline__ unsigned ord_f32(float f)
{
    int i = __float_as_int(f);
    return (i < 0) ? ~(unsigned)i : ((unsigned)i | 0x80000000u);
}

// ---------------------------------------------------------------------------
// Kernel Q: q[b][e] = sum_d a_s_q[b][d] * W[d][e]
// One thread per (b,e): 40 blocks x 128 threads. Serial fmaf chain over d
// (same order as R2); unroll-32 batches the W loads for MLP.
// ---------------------------------------------------------------------------
__global__ __launch_bounds__(128) void q_kernel(
    const float* __restrict__ a_s_q,
    const float* __restrict__ W)
{
    __shared__ float aq[D2];
    const int b = blockIdx.x;
    const int e = blockIdx.y * 128 + threadIdx.x;

    for (int i = threadIdx.x; i < D2; i += 128) aq[i] = a_s_q[b * D2 + i];
    __syncthreads();

    float s = 0.f;
    #pragma unroll 32
    for (int d = 0; d < D2; ++d) s = fmaf(aq[d], W[d * D2 + e], s);
    g_q[b * D2 + e] = s;
}

// ---------------------------------------------------------------------------
// Kernel S: scores + top-10 selection + small outputs.
// Phase 2: identical FP order to R2 (4 threads per k, stride-4, shfl 1 then 2).
// Phase 3: warp-parallel selection, bit-identical to strict-> serial scan.
// ---------------------------------------------------------------------------
__global__ __launch_bounds__(256) void score_topk_kernel(
    const float* __restrict__ a_s_r,
    const int*   __restrict__ ratings,
    float* __restrict__ out)
{
    __shared__ float q[D2];
    __shared__ float sc[Kk];

    const int b = blockIdx.x;
    const int tid = threadIdx.x;

    for (int i = tid; i < D2; i += 256) q[i] = g_q[b * D2 + i];
    __syncthreads();

    {
        const int k = tid >> 2;
        const int sub = tid & 3;
        const float* ar = a_s_r + ((size_t)(b * Kk + k)) * D2;
        float s = 0.f;
        #pragma unroll 16
        for (int e = sub; e < D2; e += 4) s = fmaf(q[e], ar[e], s);
        s += __shfl_xor_sync(0xFFFFFFFFu, s, 1);
        s += __shfl_xor_sync(0xFFFFFFFFu, s, 2);
        if (sub == 0) sc[k] = xla_tanhf(s);
    }
    __syncthreads();

    if (tid < 32) {
        const int lane = tid;
        // key = ord(score) << 7 | (127 - k): max key == max score, min index
        unsigned long long k0 =
            ((unsigned long long)ord_f32(sc[lane]) << 7) | (unsigned)(127 - lane);
        unsigned long long k1 =
            ((unsigned long long)ord_f32(sc[lane + 32]) << 7) | (unsigned)(127 - (lane + 32));

        #pragma unroll
        for (int t = 0; t < TOPK; ++t) {
            unsigned long long m = (k0 > k1) ? k0 : k1;
            #pragma unroll
            for (int o = 16; o > 0; o >>= 1) {
                unsigned long long other = __shfl_xor_sync(0xFFFFFFFFu, m, o);
                if (other > m) m = other;
            }
            const int bk = 127 - (int)(m & 127u);
            if (lane == 0) {
                out[OFF_SCORES  + b * TOPK + t] = sc[bk];
                out[OFF_RATINGS + b * TOPK + t] = (float)ratings[b * Kk + bk];
                out[OFF_IDX     + b * TOPK + t] = (float)bk;
                g_topk_idx[b * TOPK + t] = bk;
            }
            if (bk == lane)      k0 = 0ull;
            if (bk == lane + 32) k1 = 0ull;
        }
    }
}

// ---------------------------------------------------------------------------
// Kernel G: fused vectorized gather (unchanged from R2; 26.5us @ 58.8% DRAM)
// ---------------------------------------------------------------------------
__global__ __launch_bounds__(256) void gather_kernel(
    const float4* __restrict__ s_r,
    const float4* __restrict__ h_r,
    const float4* __restrict__ r_a,
    const float4* __restrict__ r_o,
    const float4* __restrict__ mask,
    const int4*   __restrict__ rb,
    const float4* __restrict__ rm,
    const int4*   __restrict__ re,
    float4* __restrict__ out4)
{
    __shared__ int idx_s[Bq * TOPK];
    if (threadIdx.x < Bq * TOPK) idx_s[threadIdx.x] = g_topk_idx[threadIdx.x];
    __syncthreads();

    const unsigned stride = gridDim.x * blockDim.x;
    for (unsigned g = blockIdx.x * blockDim.x + threadIdx.x; g < G_TOTAL; g += stride) {
        if (g >= G_SR_END && g < G_HR_END) {
            const unsigned local = g - G_SR_END;
            const unsigned row = local >> 16;
            const unsigned iv  = local & 0xFFFFu;
            const unsigned b   = row / TOPK;
            const unsigned k   = (unsigned)idx_s[row];
            out4[V4_HR + local] = h_r[(b * Kk + k) * 65536u + iv];
        } else if (g < G_SR_END) {
            const unsigned row = g >> 9;
            const unsigned iv  = g & 511u;
            const unsigned b   = row / TOPK;
            const unsigned k   = (unsigned)idx_s[row];
            out4[V4_SR + g] = s_r[(b * Kk + k) * 512u + iv];
        } else if (g < G_RA_END) {
            const unsigned local = g - G_HR_END;
            const unsigned row = local >> 7;
            const unsigned iv  = local & 127u;
            const unsigned b   = row / TOPK;
            const unsigned k   = (unsigned)idx_s[row];
            out4[V4_RA + local] = r_a[(b * Kk + k) * 128u + iv];
        } else if (g < G_RO_END) {
            const unsigned local = g - G_RA_END;
            const unsigned row = local >> 7;
            const unsigned iv  = local & 127u;
            const unsigned b   = row / TOPK;
            const unsigned k   = (unsigned)idx_s[row];
            out4[V4_RO + local] = r_o[(b * Kk + k) * 128u + iv];
        } else if (g < G_MK_END) {
            const unsigned local = g - G_RO_END;
            const unsigned b = local / TOPK;
            const unsigned k = (unsigned)idx_s[local];
            out4[V4_MASK + local] = mask[b * Kk + k];
        } else if (g < G_RB_END) {
            const unsigned local = g - G_MK_END;
            const unsigned row = local >> 5;
            const unsigned iv  = local & 31u;
            const unsigned b   = row / TOPK;
            const unsigned k   = (unsigned)idx_s[row];
            const int4 v = rb[(b * Kk + k) * 32u + iv];
            out4[V4_RB + local] = make_float4((float)v.x, (float)v.y, (float)v.z, (float)v.w);
        } else if (g < G_RM_END) {
            const unsigned local = g - G_RB_END;
            const unsigned row = local >> 5;
            const unsigned iv  = local & 31u;
            const unsigned b   = row / TOPK;
            const unsigned k   = (unsigned)idx_s[row];
            out4[V4_RM + local] = rm[(b * Kk + k) * 32u + iv];
        } else {
            const unsigned local = g - G_RM_END;
            const unsigned row = local >> 5;
            const unsigned iv  = local & 31u;
            const unsigned b   = row / TOPK;
            const unsigned k   = (unsigned)idx_s[row];
            const int4 v = re[(b * Kk + k) * 32u + iv];
            out4[V4_RE + local] = make_float4((float)v.x, (float)v.y, (float)v.z, (float)v.w);
        }
    }
}

// ---------------------------------------------------------------------------
extern "C" void kernel_launch(void* const* d_in, const int* in_sizes, int n_in,
                              void* d_out, int out_size)
{
    const float* a_s_q   = (const float*)d_in[0];
    const float* a_s_r   = (const float*)d_in[1];
    const float* W       = (const float*)d_in[2];
    const float* s_r     = (const float*)d_in[3];
    const float* h_r     = (const float*)d_in[4];
    const float* r_a     = (const float*)d_in[5];
    const float* r_o     = (const float*)d_in[6];
    const float* mask    = (const float*)d_in[7];
    const int*   rb      = (const int*)d_in[8];
    const float* rm      = (const float*)d_in[9];
    const int*   ratings = (const int*)d_in[10];
    const int*   re      = (const int*)d_in[11];
    float* out = (float*)d_out;

    q_kernel<<<dim3(Bq, 5), 128>>>(a_s_q, W);
    score_topk_kernel<<<Bq, 256>>>(a_s_r, ratings, out);
    gather_kernel<<<4736, 256>>>(
        (const float4*)s_r, (const float4*)h_r, (const float4*)r_a,
        (const float4*)r_o, (const float4*)mask, (const int4*)rb,
        (const float4*)rm, (const int4*)re, (float4*)out);
}

// round 4
// speedup vs baseline: 3.0034x; 3.0034x over previous
#include <cuda_runtime.h>
#include <cuda_bf16.h>

// ---------------------------------------------------------------------------
// Model_70222715289880: bilinear score -> top-k(10/64) -> gather of 10 tensors
// B=8, K=64, TOPK=10, N_R=4, L_R=128, H=512, D=128, D2=640.
//
// R4: same FP summation order as the passing R2/R3 kernels (bit-identical
// chains -> same tanh-plateau tie structure -> same top-k), but with explicit
// double-buffered register prefetch so the serial fmaf chains no longer
// expose one full memory latency per load (R3 q_kernel: MLP=1, 153us).
// ---------------------------------------------------------------------------

#define Bq   8
#define Kk   64
#define TOPK 10
#define D2   640

#define OFF_SCORES   0
#define OFF_RATINGS  21238160
#define OFF_IDX      21248480

// vec4 (float4) offsets of gathered segments in dst
#define V4_SR    20u
#define V4_HR    40980u
#define V4_RA    5283860u
#define V4_RO    5294100u
#define V4_MASK  5304340u
#define V4_RB    5304420u
#define V4_RM    5306980u
#define V4_RE    5309560u

// gather-index range boundaries, in vec4 units
#define G_SR_END   40960u
#define G_HR_END   5283840u
#define G_RA_END   5294080u
#define G_RO_END   5304320u
#define G_MK_END   5304400u
#define G_RB_END   5306960u
#define G_RM_END   5309520u
#define G_RE_END   5312080u
#define G_TOTAL    5312080u

__device__ int   g_topk_idx[Bq * TOPK];
__device__ float g_q[Bq * D2];

// ---------------------------------------------------------------------------
// XLA's tanh (Eigen generic_fast_tanh_float as emitted by elemental_ir_emitter)
// ---------------------------------------------------------------------------
__device__ __forceinline__ float xla_tanhf(float x)
{
    const float kClamp = 7.90531110763549805f;
    float xc = fmaxf(-kClamp, fminf(x, kClamp));
    float x2 = xc * xc;

    float p = fmaf(x2, -2.76076847742355e-16f, 2.00018790482477e-13f);
    p = fmaf(x2, p, -8.60467152213735e-11f);
    p = fmaf(x2, p,  5.12229709037114e-08f);
    p = fmaf(x2, p,  1.48572235717979e-05f);
    p = fmaf(x2, p,  6.37261928875436e-04f);
    p = fmaf(x2, p,  4.89352455891786e-03f);
    p = xc * p;

    float q = fmaf(x2, 1.19825839466702e-06f, 1.18534705686654e-04f);
    q = fmaf(x2, q, 2.26843463243900e-03f);
    q = fmaf(x2, q, 4.89352518554385e-03f);

    float r = p / q;
    return (fabsf(x) < 0.0004f) ? x : r;
}

// total-order key on float (ascending)
__device__ __forceinline__ unsigned ord_f32(float f)
{
    int i = __float_as_int(f);
    return (i < 0) ? ~(unsigned)i : ((unsigned)i | 0x80000000u);
}

// ---------------------------------------------------------------------------
// Kernel Q: q[b][e] = sum_d a_s_q[b][d] * W[d][e], serial-d chain (FP order
// identical to R2/R3). Explicit prefetch: 32 independent LDGs for batch c+1
// are issued back-to-back BEFORE the fmaf block of batch c.
// ---------------------------------------------------------------------------
#define QPF 32
__global__ __launch_bounds__(128) void q_kernel(
    const float* __restrict__ a_s_q,
    const float* __restrict__ W)
{
    __shared__ float aq[D2];
    const int b = blockIdx.x;
    const int e = blockIdx.y * 128 + threadIdx.x;

    for (int i = threadIdx.x; i < D2; i += 128) aq[i] = a_s_q[b * D2 + i];
    __syncthreads();

    const float* w = W + e;          // column e, stride D2
    float rb[QPF], nb[QPF];
    #pragma unroll
    for (int i = 0; i < QPF; ++i) rb[i] = w[i * D2];

    float s = 0.f;
    for (int base = 0; base < D2; base += QPF) {
        if (base + QPF < D2) {
            #pragma unroll
            for (int i = 0; i < QPF; ++i) nb[i] = w[(base + QPF + i) * D2];
        }
        #pragma unroll
        for (int i = 0; i < QPF; ++i) s = fmaf(aq[base + i], rb[i], s);
        if (base + QPF < D2) {
            #pragma unroll
            for (int i = 0; i < QPF; ++i) rb[i] = nb[i];
        }
    }
    g_q[b * D2 + e] = s;
}

// ---------------------------------------------------------------------------
// Kernel S: scores + top-10 + small outputs. Dot phase: 4 threads per k,
// stride-4 chains + shfl pairs — FP order identical to R2/R3 — with explicit
// 16-deep register prefetch for the a_s_r loads.
// ---------------------------------------------------------------------------
#define SPF 16
__global__ __launch_bounds__(256) void score_topk_kernel(
    const float* __restrict__ a_s_r,
    const int*   __restrict__ ratings,
    float* __restrict__ out)
{
    __shared__ float q[D2];
    __shared__ float sc[Kk];

    const int b = blockIdx.x;
    const int tid = threadIdx.x;

    for (int i = tid; i < D2; i += 256) q[i] = g_q[b * D2 + i];
    __syncthreads();

    {
        const int k = tid >> 2;
        const int sub = tid & 3;
        const float* ar = a_s_r + ((size_t)(b * Kk + k)) * D2 + sub;  // stride 4

        float rb[SPF], nb[SPF];
        #pragma unroll
        for (int i = 0; i < SPF; ++i) rb[i] = ar[4 * i];

        float s = 0.f;
        // 160 chain steps, batches of 16
        for (int base = 0; base < 160; base += SPF) {
            if (base + SPF < 160) {
                #pragma unroll
                for (int i = 0; i < SPF; ++i) nb[i] = ar[4 * (base + SPF + i)];
            }
            #pragma unroll
            for (int i = 0; i < SPF; ++i)
                s = fmaf(q[sub + 4 * (base + i)], rb[i], s);
            if (base + SPF < 160) {
                #pragma unroll
                for (int i = 0; i < SPF; ++i) rb[i] = nb[i];
            }
        }
        s += __shfl_xor_sync(0xFFFFFFFFu, s, 1);
        s += __shfl_xor_sync(0xFFFFFFFFu, s, 2);
        if (sub == 0) sc[k] = xla_tanhf(s);
    }
    __syncthreads();

    if (tid < 32) {
        const int lane = tid;
        // key = ord(score) << 7 | (127 - k): max key == max score, min index
        unsigned long long k0 =
            ((unsigned long long)ord_f32(sc[lane]) << 7) | (unsigned)(127 - lane);
        unsigned long long k1 =
            ((unsigned long long)ord_f32(sc[lane + 32]) << 7) | (unsigned)(127 - (lane + 32));

        #pragma unroll
        for (int t = 0; t < TOPK; ++t) {
            unsigned long long m = (k0 > k1) ? k0 : k1;
            #pragma unroll
            for (int o = 16; o > 0; o >>= 1) {
                unsigned long long other = __shfl_xor_sync(0xFFFFFFFFu, m, o);
                if (other > m) m = other;
            }
            const int bk = 127 - (int)(m & 127u);
            if (lane == 0) {
                out[OFF_SCORES  + b * TOPK + t] = sc[bk];
                out[OFF_RATINGS + b * TOPK + t] = (float)ratings[b * Kk + bk];
                out[OFF_IDX     + b * TOPK + t] = (float)bk;
                g_topk_idx[b * TOPK + t] = bk;
            }
            if (bk == lane)      k0 = 0ull;
            if (bk == lane + 32) k1 = 0ull;
        }
    }
}

// ---------------------------------------------------------------------------
// Kernel G: fused vectorized gather (unchanged; 26.5us @ 58.8% DRAM)
// ---------------------------------------------------------------------------
__global__ __launch_bounds__(256) void gather_kernel(
    const float4* __restrict__ s_r,
    const float4* __restrict__ h_r,
    const float4* __restrict__ r_a,
    const float4* __restrict__ r_o,
    const float4* __restrict__ mask,
    const int4*   __restrict__ rb,
    const float4* __restrict__ rm,
    const int4*   __restrict__ re,
    float4* __restrict__ out4)
{
    __shared__ int idx_s[Bq * TOPK];
    if (threadIdx.x < Bq * TOPK) idx_s[threadIdx.x] = g_topk_idx[threadIdx.x];
    __syncthreads();

    const unsigned stride = gridDim.x * blockDim.x;
    for (unsigned g = blockIdx.x * blockDim.x + threadIdx.x; g < G_TOTAL; g += stride) {
        if (g >= G_SR_END && g < G_HR_END) {
            const unsigned local = g - G_SR_END;
            const unsigned row = local >> 16;
            const unsigned iv  = local & 0xFFFFu;
            const unsigned b   = row / TOPK;
            const unsigned k   = (unsigned)idx_s[row];
            out4[V4_HR + local] = h_r[(b * Kk + k) * 65536u + iv];
        } else if (g < G_SR_END) {
            const unsigned row = g >> 9;
            const unsigned iv  = g & 511u;
            const unsigned b   = row / TOPK;
            const unsigned k   = (unsigned)idx_s[row];
            out4[V4_SR + g] = s_r[(b * Kk + k) * 512u + iv];
        } else if (g < G_RA_END) {
            const unsigned local = g - G_HR_END;
            const unsigned row = local >> 7;
            const unsigned iv  = local & 127u;
            const unsigned b   = row / TOPK;
            const unsigned k   = (unsigned)idx_s[row];
            out4[V4_RA + local] = r_a[(b * Kk + k) * 128u + iv];
        } else if (g < G_RO_END) {
            const unsigned local = g - G_RA_END;
            const unsigned row = local >> 7;
            const unsigned iv  = local & 127u;
            const unsigned b   = row / TOPK;
            const unsigned k   = (unsigned)idx_s[row];
            out4[V4_RO + local] = r_o[(b * Kk + k) * 128u + iv];
        } else if (g < G_MK_END) {
            const unsigned local = g - G_RO_END;
            const unsigned b = local / TOPK;
            const unsigned k = (unsigned)idx_s[local];
            out4[V4_MASK + local] = mask[b * Kk + k];
        } else if (g < G_RB_END) {
            const unsigned local = g - G_MK_END;
            const unsigned row = local >> 5;
            const unsigned iv  = local & 31u;
            const unsigned b   = row / TOPK;
            const unsigned k   = (unsigned)idx_s[row];
            const int4 v = rb[(b * Kk + k) * 32u + iv];
            out4[V4_RB + local] = make_float4((float)v.x, (float)v.y, (float)v.z, (float)v.w);
        } else if (g < G_RM_END) {
            const unsigned local = g - G_RB_END;
            const unsigned row = local >> 5;
            const unsigned iv  = local & 31u;
            const unsigned b   = row / TOPK;
            const unsigned k   = (unsigned)idx_s[row];
            out4[V4_RM + local] = rm[(b * Kk + k) * 32u + iv];
        } else {
            const unsigned local = g - G_RM_END;
            const unsigned row = local >> 5;
            const unsigned iv  = local & 31u;
            const unsigned b   = row / TOPK;
            const unsigned k   = (unsigned)idx_s[row];
            const int4 v = re[(b * Kk + k) * 32u + iv];
            out4[V4_RE + local] = make_float4((float)v.x, (float)v.y, (float)v.z, (float)v.w);
        }
    }
}

// ---------------------------------------------------------------------------
extern "C" void kernel_launch(void* const* d_in, const int* in_sizes, int n_in,
                              void* d_out, int out_size)
{
    const float* a_s_q   = (const float*)d_in[0];
    const float* a_s_r   = (const float*)d_in[1];
    const float* W       = (const float*)d_in[2];
    const float* s_r     = (const float*)d_in[3];
    const float* h_r     = (const float*)d_in[4];
    const float* r_a     = (const float*)d_in[5];
    const float* r_o     = (const float*)d_in[6];
    const float* mask    = (const float*)d_in[7];
    const int*   rb      = (const int*)d_in[8];
    const float* rm      = (const float*)d_in[9];
    const int*   ratings = (const int*)d_in[10];
    const int*   re      = (const int*)d_in[11];
    float* out = (float*)d_out;

    q_kernel<<<dim3(Bq, 5), 128>>>(a_s_q, W);
    score_topk_kernel<<<Bq, 256>>>(a_s_r, ratings, out);
    gather_kernel<<<4736, 256>>>(
        (const float4*)s_r, (const float4*)h_r, (const float4*)r_a,
        (const float4*)r_o, (const float4*)mask, (const int4*)rb,
        (const float4*)rm, (const int4*)re, (float4*)out);
}